// round 4
// baseline (speedup 1.0000x reference)
#include <cuda_runtime.h>
#include <math.h>

#define Nn   50000
#define Ee   800000
#define ENb  (Ee + Nn)
#define Cc   128
#define Hh   4
#define Gg   512
#define OUTC 100
#define NEG  0.2f
#define EPSf 1e-16f

// ---- scratch (device globals: no allocations allowed) ----
__device__ __align__(16) float g_feat[Nn * Cc];   // layer output / next layer input
__device__ __align__(16) float g_h[Nn * Cc];      // transformed features (gather source)
__device__ __align__(16) float g_asrc[Nn * Hh];
__device__ __align__(16) float g_adst[Nn * Hh];
__device__ int   g_rowptr[Nn + 1];
__device__ int   g_cursor[Nn];
__device__ int   g_col[ENb];
__device__ __align__(16) float g_sums[Gg * Cc];
__device__ float g_cnt[Gg];

// ---------------- init: deg=1 (self loop), zero pool accumulators ----------------
__global__ void k_init() {
    int i = blockIdx.x * 256 + threadIdx.x;
    if (i < Gg * Cc) g_sums[i] = 0.f;
    if (i < Gg)      g_cnt[i]  = 0.f;
    if (i < Nn)      g_cursor[i] = 1;   // self loop counted
}

// ---------------- histogram over dst ----------------
__global__ void k_hist(const int* __restrict__ ei) {
    int e = blockIdx.x * 256 + threadIdx.x;
    if (e < Ee) {
        int d = ei[Ee + e];
        atomicAdd(&g_cursor[d], 1);
    }
}

// ---------------- single-block exclusive scan (N=50000) ----------------
__global__ void k_scan() {
    __shared__ int s[1024];
    int t = threadIdx.x;
    const int PER = (Nn + 1023) / 1024;   // 49
    int base = t * PER;
    int sum = 0;
    for (int i = 0; i < PER; i++) {
        int idx = base + i;
        if (idx < Nn) sum += g_cursor[idx];
    }
    s[t] = sum;
    __syncthreads();
    for (int o = 1; o < 1024; o <<= 1) {
        int u = (t >= o) ? s[t - o] : 0;
        __syncthreads();
        s[t] += u;
        __syncthreads();
    }
    int off = s[t] - sum;                 // exclusive prefix
    for (int i = 0; i < PER; i++) {
        int idx = base + i;
        if (idx < Nn) {
            int d = g_cursor[idx];
            g_rowptr[idx] = off;
            g_cursor[idx] = off;          // scatter cursor
            off += d;
        }
    }
    if (t == 1023) g_rowptr[Nn] = s[1023];
}

// ---------------- scatter edges + self loops into CSR ----------------
__global__ void k_scatter(const int* __restrict__ ei) {
    int e = blockIdx.x * 256 + threadIdx.x;
    if (e >= ENb) return;
    if (e < Ee) {
        int d = ei[Ee + e];
        int pos = atomicAdd(&g_cursor[d], 1);
        g_col[pos] = ei[e];
    } else {
        int n = e - Ee;
        int pos = atomicAdd(&g_cursor[n], 1);
        g_col[pos] = n;
    }
}

// ---------------- fused GEMM + attention logits ----------------
// g_h[N,128] = X[N,128] @ W[128,128]^T ; g_asrc/g_adst[N,4] = per-head dots.
// BM=128, BN=128, BK=16, 256 threads, 8x8 per thread. One block covers a full
// output row, so att logits are computed from register accumulators.
template<bool FROM_GLOBAL>
__global__ __launch_bounds__(256) void k_gemm(const float* __restrict__ X,
                                              const float* __restrict__ W,
                                              const float* __restrict__ AS,
                                              const float* __restrict__ AD) {
    __shared__ __align__(16) float ftT[16][132];   // [k][row]
    __shared__ __align__(16) float wtT[16][132];   // [k][col]
    const float* __restrict__ src = FROM_GLOBAL ? (const float*)g_feat : X;
    int t = threadIdx.x;
    int rowBlk = blockIdx.x * 128;
    int tx = t & 15, ty = t >> 4;
    int r0 = ty << 3;                // 0..120
    int c0 = tx << 3;                // 0..120
    float acc[8][8];
#pragma unroll
    for (int j = 0; j < 8; j++)
#pragma unroll
        for (int l = 0; l < 8; l++) acc[j][l] = 0.f;

    for (int kb = 0; kb < 128; kb += 16) {
        // load A tile: 128 rows x 16 k = 512 float4, 2 per thread
#pragma unroll
        for (int i = 0; i < 2; i++) {
            int u = t + i * 256;
            int row = u & 127, kq = u >> 7;       // kq in 0..3
            int grow = rowBlk + row;
            float4 v = make_float4(0.f, 0.f, 0.f, 0.f);
            if (grow < Nn) v = *(const float4*)&src[grow * 128 + kb + kq * 4];
            ftT[kq * 4 + 0][row] = v.x;
            ftT[kq * 4 + 1][row] = v.y;
            ftT[kq * 4 + 2][row] = v.z;
            ftT[kq * 4 + 3][row] = v.w;
        }
        // load W tile: 128 cols x 16 k
#pragma unroll
        for (int i = 0; i < 2; i++) {
            int u = t + i * 256;
            int col = u & 127, kq = u >> 7;
            float4 v = *(const float4*)&W[col * 128 + kb + kq * 4];
            wtT[kq * 4 + 0][col] = v.x;
            wtT[kq * 4 + 1][col] = v.y;
            wtT[kq * 4 + 2][col] = v.z;
            wtT[kq * 4 + 3][col] = v.w;
        }
        __syncthreads();
#pragma unroll
        for (int k = 0; k < 16; k++) {
            float4 a0 = *(const float4*)&ftT[k][r0];
            float4 a1 = *(const float4*)&ftT[k][r0 + 4];
            float4 b0 = *(const float4*)&wtT[k][c0];
            float4 b1 = *(const float4*)&wtT[k][c0 + 4];
            float av[8] = {a0.x, a0.y, a0.z, a0.w, a1.x, a1.y, a1.z, a1.w};
            float bv[8] = {b0.x, b0.y, b0.z, b0.w, b1.x, b1.y, b1.z, b1.w};
#pragma unroll
            for (int j = 0; j < 8; j++)
#pragma unroll
                for (int l = 0; l < 8; l++)
                    acc[j][l] = fmaf(av[j], bv[l], acc[j][l]);
        }
        __syncthreads();
    }

    // att vectors for this thread's 8 columns (head = c0/32 constant per thread)
    float4 s0 = *(const float4*)&AS[c0];
    float4 s1 = *(const float4*)&AS[c0 + 4];
    float4 d0 = *(const float4*)&AD[c0];
    float4 d1 = *(const float4*)&AD[c0 + 4];
    float sv[8] = {s0.x, s0.y, s0.z, s0.w, s1.x, s1.y, s1.z, s1.w};
    float dv[8] = {d0.x, d0.y, d0.z, d0.w, d1.x, d1.y, d1.z, d1.w};

#pragma unroll
    for (int j = 0; j < 8; j++) {
        int row = rowBlk + r0 + j;
        float ps = 0.f, pd = 0.f;
#pragma unroll
        for (int l = 0; l < 8; l++) {
            ps = fmaf(acc[j][l], sv[l], ps);
            pd = fmaf(acc[j][l], dv[l], pd);
        }
        // reduce over the 4 threads covering one head (lane bits 0,1 = tx bits 0,1)
        ps += __shfl_xor_sync(0xffffffffu, ps, 1);
        pd += __shfl_xor_sync(0xffffffffu, pd, 1);
        ps += __shfl_xor_sync(0xffffffffu, ps, 2);
        pd += __shfl_xor_sync(0xffffffffu, pd, 2);
        if (row < Nn) {
            float4 v0 = make_float4(acc[j][0], acc[j][1], acc[j][2], acc[j][3]);
            float4 v1 = make_float4(acc[j][4], acc[j][5], acc[j][6], acc[j][7]);
            *(float4*)&g_h[row * 128 + c0]     = v0;
            *(float4*)&g_h[row * 128 + c0 + 4] = v1;
            if ((tx & 3) == 0) {
                int head = tx >> 2;
                g_asrc[row * 4 + head] = ps;
                g_adst[row * 4 + head] = pd;
            }
        }
    }
}

__device__ __forceinline__ float lrelu(float x) { return x > 0.f ? x : NEG * x; }

// ---------------- per-dst-node softmax + aggregation, single pass ----------------
// exp(a)/sum(exp(a)) == exp(a-m)/sum(exp(a-m)); logits are O(1) so no stabilizer.
__global__ __launch_bounds__(256) void k_agg(const float* __restrict__ bias) {
    int n = (blockIdx.x * 256 + threadIdx.x) >> 5;
    int lane = threadIdx.x & 31;
    if (n >= Nn) return;
    int start = g_rowptr[n], end = g_rowptr[n + 1];
    int head = lane >> 3;
    int ch = lane << 2;
    float adh = g_adst[n * 4 + head];

    float4 acc = make_float4(0.f, 0.f, 0.f, 0.f);
    float den = 0.f;
    int e = start;
    for (; e + 1 < end; e += 2) {
        int s0 = g_col[e], s1 = g_col[e + 1];
        float a0 = g_asrc[(s0 << 2) + head] + adh;
        float a1 = g_asrc[(s1 << 2) + head] + adh;
        float4 h0 = *(const float4*)(g_h + s0 * 128 + ch);
        float4 h1 = *(const float4*)(g_h + s1 * 128 + ch);
        float w0 = __expf(lrelu(a0));
        float w1 = __expf(lrelu(a1));
        den += w0 + w1;
        acc.x += w0 * h0.x + w1 * h1.x;
        acc.y += w0 * h0.y + w1 * h1.y;
        acc.z += w0 * h0.z + w1 * h1.z;
        acc.w += w0 * h0.w + w1 * h1.w;
    }
    if (e < end) {
        int s0 = g_col[e];
        float a0 = g_asrc[(s0 << 2) + head] + adh;
        float4 h0 = *(const float4*)(g_h + s0 * 128 + ch);
        float w0 = __expf(lrelu(a0));
        den += w0;
        acc.x += w0 * h0.x;
        acc.y += w0 * h0.y;
        acc.z += w0 * h0.z;
        acc.w += w0 * h0.w;
    }
    float inv = 1.f / (den + EPSf);
    float4 b4 = *(const float4*)(bias + ch);
    float vx = acc.x * inv + b4.x;
    float vy = acc.y * inv + b4.y;
    float vz = acc.z * inv + b4.z;
    float vw = acc.w * inv + b4.w;
    // ELU
    vx = vx > 0.f ? vx : expm1f(vx);
    vy = vy > 0.f ? vy : expm1f(vy);
    vz = vz > 0.f ? vz : expm1f(vz);
    vw = vw > 0.f ? vw : expm1f(vw);
    *(float4*)&g_feat[n * 128 + ch] = make_float4(vx, vy, vz, vw);
}

// ---------------- global mean pool (atomics over g_feat) ----------------
__global__ __launch_bounds__(256) void k_pool(const int* __restrict__ batch) {
    int n = (blockIdx.x * 256 + threadIdx.x) >> 5;
    int lane = threadIdx.x & 31;
    if (n >= Nn) return;
    int g = batch[n];
    float4 v = *(const float4*)(g_feat + n * 128 + (lane << 2));
    float* sp = &g_sums[g * 128 + (lane << 2)];
    atomicAdd(sp + 0, v.x);
    atomicAdd(sp + 1, v.y);
    atomicAdd(sp + 2, v.z);
    atomicAdd(sp + 3, v.w);
    if (lane == 0) atomicAdd(&g_cnt[g], 1.f);
}

// ---------------- final FC: out[G,100] = (sums/cnt) @ fcW^T + fcb ----------------
__global__ void k_fc(const float* __restrict__ fcW,
                     const float* __restrict__ fcb,
                     float* __restrict__ out) {
    int i = blockIdx.x * 256 + threadIdx.x;
    if (i >= Gg * OUTC) return;
    int g = i / OUTC, o = i - g * OUTC;
    float inv = 1.f / fmaxf(g_cnt[g], 1.f);
    const float* sr = &g_sums[g * 128];
    const float* wr = &fcW[o * 128];
    float s = 0.f;
#pragma unroll
    for (int c = 0; c < 128; c++) s = fmaf(sr[c], wr[c], s);
    out[i] = s * inv + fcb[o];
}

extern "C" void kernel_launch(void* const* d_in, const int* in_sizes, int n_in,
                              void* d_out, int out_size) {
    const float* x     = (const float*)d_in[0];
    const int*   ei    = (const int*)d_in[1];    // int64 in reference -> staged int32
    const int*   batch = (const int*)d_in[2];
    const float* W1 = (const float*)d_in[3];
    const float* as1 = (const float*)d_in[4];
    const float* ad1 = (const float*)d_in[5];
    const float* b1 = (const float*)d_in[6];
    const float* W2 = (const float*)d_in[7];
    const float* as2 = (const float*)d_in[8];
    const float* ad2 = (const float*)d_in[9];
    const float* b2 = (const float*)d_in[10];
    const float* W3 = (const float*)d_in[11];
    const float* as3 = (const float*)d_in[12];
    const float* ad3 = (const float*)d_in[13];
    const float* b3 = (const float*)d_in[14];
    const float* fcW = (const float*)d_in[15];
    const float* fcb = (const float*)d_in[16];
    float* out = (float*)d_out;

    // CSR build (once per call) + pool accumulator zeroing
    k_init<<<256, 256>>>();
    k_hist<<<(Ee + 255) / 256, 256>>>(ei);
    k_scan<<<1, 1024>>>();
    k_scatter<<<(ENb + 255) / 256, 256>>>(ei);

    int gemmBlocks = (Nn + 127) / 128;   // 391
    int aggBlocks = (Nn + 7) / 8;

    // layer 1
    k_gemm<false><<<gemmBlocks, 256>>>(x, W1, as1, ad1);
    k_agg<<<aggBlocks, 256>>>(b1);
    // layer 2
    k_gemm<true><<<gemmBlocks, 256>>>(nullptr, W2, as2, ad2);
    k_agg<<<aggBlocks, 256>>>(b2);
    // layer 3
    k_gemm<true><<<gemmBlocks, 256>>>(nullptr, W3, as3, ad3);
    k_agg<<<aggBlocks, 256>>>(b3);

    // pool + fc
    k_pool<<<aggBlocks, 256>>>(batch);
    k_fc<<<(Gg * OUTC + 255) / 256, 256>>>(fcW, fcb, out);
}

// round 5
// speedup vs baseline: 1.4174x; 1.4174x over previous
#include <cuda_runtime.h>
#include <math.h>

#define Nn   50000
#define Ee   800000
#define ENb  (Ee + Nn)
#define Cc   128
#define Hh   4
#define Gg   512
#define OUTC 100
#define NEG  0.2f
#define EPSf 1e-16f

// ---- scratch (device globals: no allocations allowed) ----
__device__ __align__(16) float g_feat[Nn * Cc];   // layer output / next layer input
__device__ __align__(16) float g_h[Nn * Cc];      // transformed features (gather source)
__device__ __align__(16) float g_asrc[Nn * Hh];
__device__ __align__(16) float g_adst[Nn * Hh];
__device__ int   g_rowptr[Nn + 1];
__device__ int   g_cursor[Nn];
__device__ int   g_col[ENb];
__device__ __align__(16) float g_sums[Gg * Cc];
__device__ float g_cnt[Gg];

// ---------------- init: deg=1 (self loop), zero pool accumulators ----------------
__global__ void k_init() {
    int i = blockIdx.x * 256 + threadIdx.x;
    if (i < Gg * Cc) g_sums[i] = 0.f;
    if (i < Gg)      g_cnt[i]  = 0.f;
    if (i < Nn)      g_cursor[i] = 1;   // self loop counted
}

// ---------------- histogram over dst ----------------
__global__ void k_hist(const int* __restrict__ ei) {
    int e = blockIdx.x * 256 + threadIdx.x;
    if (e < Ee) {
        int d = ei[Ee + e];
        atomicAdd(&g_cursor[d], 1);
    }
}

// ---------------- single-block exclusive scan (N=50000) ----------------
__global__ void k_scan() {
    __shared__ int s[1024];
    int t = threadIdx.x;
    const int PER = (Nn + 1023) / 1024;   // 49
    int base = t * PER;
    int sum = 0;
    for (int i = 0; i < PER; i++) {
        int idx = base + i;
        if (idx < Nn) sum += g_cursor[idx];
    }
    s[t] = sum;
    __syncthreads();
    for (int o = 1; o < 1024; o <<= 1) {
        int u = (t >= o) ? s[t - o] : 0;
        __syncthreads();
        s[t] += u;
        __syncthreads();
    }
    int off = s[t] - sum;                 // exclusive prefix
    for (int i = 0; i < PER; i++) {
        int idx = base + i;
        if (idx < Nn) {
            int d = g_cursor[idx];
            g_rowptr[idx] = off;
            g_cursor[idx] = off;          // scatter cursor
            off += d;
        }
    }
    if (t == 1023) g_rowptr[Nn] = s[1023];
}

// ---------------- scatter edges + self loops into CSR ----------------
__global__ void k_scatter(const int* __restrict__ ei) {
    int e = blockIdx.x * 256 + threadIdx.x;
    if (e >= ENb) return;
    if (e < Ee) {
        int d = ei[Ee + e];
        int pos = atomicAdd(&g_cursor[d], 1);
        g_col[pos] = ei[e];
    } else {
        int n = e - Ee;
        int pos = atomicAdd(&g_cursor[n], 1);
        g_col[pos] = n;
    }
}

// ---------------- GEMM: g_h[N,128] = X[N,128] @ W[128,128]^T ----------------
// BM=128, BN=64, BK=32, 256 threads, each computes 8x4. (R3-proven shape.)
template<bool FROM_GLOBAL>
__global__ __launch_bounds__(256) void k_gemm(const float* __restrict__ X,
                                              const float* __restrict__ W) {
    __shared__ __align__(16) float ftT[32][136];   // [k][row]
    __shared__ __align__(16) float wtT[32][72];    // [k][col]
    const float* __restrict__ src = FROM_GLOBAL ? (const float*)g_feat : X;
    int t = threadIdx.x;
    int rowBlk = blockIdx.x * 128;
    int colBlk = blockIdx.y * 64;
    int r0 = (t >> 4) << 3;          // 0..120
    int c0 = (t & 15) << 2;          // 0..60
    float acc[8][4];
#pragma unroll
    for (int j = 0; j < 8; j++)
#pragma unroll
        for (int l = 0; l < 4; l++) acc[j][l] = 0.f;

    for (int kb = 0; kb < 128; kb += 32) {
#pragma unroll
        for (int i = 0; i < 16; i++) {
            int idx = t + i * 256;
            int r = idx >> 5, k = idx & 31;
            int row = rowBlk + r;
            ftT[k][r] = (row < Nn) ? src[row * 128 + kb + k] : 0.f;
        }
#pragma unroll
        for (int i = 0; i < 8; i++) {
            int idx = t + i * 256;
            int c = idx >> 5, k = idx & 31;
            wtT[k][c] = W[(colBlk + c) * 128 + kb + k];
        }
        __syncthreads();
#pragma unroll
        for (int k = 0; k < 32; k++) {
            float4 b  = *(const float4*)&wtT[k][c0];
            float4 a0 = *(const float4*)&ftT[k][r0];
            float4 a1 = *(const float4*)&ftT[k][r0 + 4];
            float av[8] = {a0.x, a0.y, a0.z, a0.w, a1.x, a1.y, a1.z, a1.w};
#pragma unroll
            for (int j = 0; j < 8; j++) {
                acc[j][0] = fmaf(av[j], b.x, acc[j][0]);
                acc[j][1] = fmaf(av[j], b.y, acc[j][1]);
                acc[j][2] = fmaf(av[j], b.z, acc[j][2]);
                acc[j][3] = fmaf(av[j], b.w, acc[j][3]);
            }
        }
        __syncthreads();
    }
#pragma unroll
    for (int j = 0; j < 8; j++) {
        int row = rowBlk + r0 + j;
        if (row < Nn) {
            float4 v = make_float4(acc[j][0], acc[j][1], acc[j][2], acc[j][3]);
            *(float4*)&g_h[row * 128 + colBlk + c0] = v;
        }
    }
}

// ---------------- attention logits: a_src/a_dst [N,H] from g_h ----------------
__global__ void k_att(const float* __restrict__ AS,
                      const float* __restrict__ AD) {
    int i = blockIdx.x * 256 + threadIdx.x;
    if (i >= Nn * Hh) return;
    int n = i >> 2, h = i & 3;
    const float4* hv  = (const float4*)(g_h + n * 128 + h * 32);
    const float4* asv = (const float4*)(AS + h * 32);
    const float4* adv = (const float4*)(AD + h * 32);
    float s = 0.f, d = 0.f;
#pragma unroll
    for (int j = 0; j < 8; j++) {
        float4 v = hv[j], a = asv[j], b = adv[j];
        s += v.x * a.x + v.y * a.y + v.z * a.z + v.w * a.w;
        d += v.x * b.x + v.y * b.y + v.z * b.z + v.w * b.w;
    }
    g_asrc[i] = s;
    g_adst[i] = d;
}

__device__ __forceinline__ float lrelu(float x) { return x > 0.f ? x : NEG * x; }

// ---------------- per-dst-node softmax + aggregation, single pass ----------------
// exp(a)/sum(exp(a)) == exp(a-m)/sum(exp(a-m)); logits are O(1) so no stabilizer.
__global__ __launch_bounds__(256) void k_agg(const float* __restrict__ bias) {
    int n = (blockIdx.x * 256 + threadIdx.x) >> 5;
    int lane = threadIdx.x & 31;
    if (n >= Nn) return;
    int start = g_rowptr[n], end = g_rowptr[n + 1];
    int head = lane >> 3;
    int ch = lane << 2;
    float adh = g_adst[n * 4 + head];

    float4 acc = make_float4(0.f, 0.f, 0.f, 0.f);
    float den = 0.f;
    int e = start;
    for (; e + 1 < end; e += 2) {
        int s0 = g_col[e], s1 = g_col[e + 1];
        float a0 = g_asrc[(s0 << 2) + head] + adh;
        float a1 = g_asrc[(s1 << 2) + head] + adh;
        float4 h0 = *(const float4*)(g_h + s0 * 128 + ch);
        float4 h1 = *(const float4*)(g_h + s1 * 128 + ch);
        float w0 = __expf(lrelu(a0));
        float w1 = __expf(lrelu(a1));
        den += w0 + w1;
        acc.x += w0 * h0.x + w1 * h1.x;
        acc.y += w0 * h0.y + w1 * h1.y;
        acc.z += w0 * h0.z + w1 * h1.z;
        acc.w += w0 * h0.w + w1 * h1.w;
    }
    if (e < end) {
        int s0 = g_col[e];
        float a0 = g_asrc[(s0 << 2) + head] + adh;
        float4 h0 = *(const float4*)(g_h + s0 * 128 + ch);
        float w0 = __expf(lrelu(a0));
        den += w0;
        acc.x += w0 * h0.x;
        acc.y += w0 * h0.y;
        acc.z += w0 * h0.z;
        acc.w += w0 * h0.w;
    }
    float inv = 1.f / (den + EPSf);
    float4 b4 = *(const float4*)(bias + ch);
    float vx = acc.x * inv + b4.x;
    float vy = acc.y * inv + b4.y;
    float vz = acc.z * inv + b4.z;
    float vw = acc.w * inv + b4.w;
    // ELU
    vx = vx > 0.f ? vx : expm1f(vx);
    vy = vy > 0.f ? vy : expm1f(vy);
    vz = vz > 0.f ? vz : expm1f(vz);
    vw = vw > 0.f ? vw : expm1f(vw);
    *(float4*)&g_feat[n * 128 + ch] = make_float4(vx, vy, vz, vw);
}

// ---------------- global mean pool (atomics over g_feat) ----------------
__global__ __launch_bounds__(256) void k_pool(const int* __restrict__ batch) {
    int n = (blockIdx.x * 256 + threadIdx.x) >> 5;
    int lane = threadIdx.x & 31;
    if (n >= Nn) return;
    int g = batch[n];
    float4 v = *(const float4*)(g_feat + n * 128 + (lane << 2));
    float* sp = &g_sums[g * 128 + (lane << 2)];
    atomicAdd(sp + 0, v.x);
    atomicAdd(sp + 1, v.y);
    atomicAdd(sp + 2, v.z);
    atomicAdd(sp + 3, v.w);
    if (lane == 0) atomicAdd(&g_cnt[g], 1.f);
}

// ---------------- final FC: out[G,100] = (sums/cnt) @ fcW^T + fcb ----------------
__global__ void k_fc(const float* __restrict__ fcW,
                     const float* __restrict__ fcb,
                     float* __restrict__ out) {
    int i = blockIdx.x * 256 + threadIdx.x;
    if (i >= Gg * OUTC) return;
    int g = i / OUTC, o = i - g * OUTC;
    float inv = 1.f / fmaxf(g_cnt[g], 1.f);
    const float* sr = &g_sums[g * 128];
    const float* wr = &fcW[o * 128];
    float s = 0.f;
#pragma unroll
    for (int c = 0; c < 128; c++) s = fmaf(sr[c], wr[c], s);
    out[i] = s * inv + fcb[o];
}

extern "C" void kernel_launch(void* const* d_in, const int* in_sizes, int n_in,
                              void* d_out, int out_size) {
    const float* x     = (const float*)d_in[0];
    const int*   ei    = (const int*)d_in[1];    // int64 in reference -> staged int32
    const int*   batch = (const int*)d_in[2];
    const float* W1 = (const float*)d_in[3];
    const float* as1 = (const float*)d_in[4];
    const float* ad1 = (const float*)d_in[5];
    const float* b1 = (const float*)d_in[6];
    const float* W2 = (const float*)d_in[7];
    const float* as2 = (const float*)d_in[8];
    const float* ad2 = (const float*)d_in[9];
    const float* b2 = (const float*)d_in[10];
    const float* W3 = (const float*)d_in[11];
    const float* as3 = (const float*)d_in[12];
    const float* ad3 = (const float*)d_in[13];
    const float* b3 = (const float*)d_in[14];
    const float* fcW = (const float*)d_in[15];
    const float* fcb = (const float*)d_in[16];
    float* out = (float*)d_out;

    // CSR build (once per call) + pool accumulator zeroing
    k_init<<<256, 256>>>();
    k_hist<<<(Ee + 255) / 256, 256>>>(ei);
    k_scan<<<1, 1024>>>();
    k_scatter<<<(ENb + 255) / 256, 256>>>(ei);

    dim3 gg((Nn + 127) / 128, 2);
    int aggBlocks = (Nn + 7) / 8;
    int attBlocks = (Nn * Hh + 255) / 256;

    // layer 1
    k_gemm<false><<<gg, 256>>>(x, W1);
    k_att<<<attBlocks, 256>>>(as1, ad1);
    k_agg<<<aggBlocks, 256>>>(b1);
    // layer 2
    k_gemm<true><<<gg, 256>>>(nullptr, W2);
    k_att<<<attBlocks, 256>>>(as2, ad2);
    k_agg<<<aggBlocks, 256>>>(b2);
    // layer 3
    k_gemm<true><<<gg, 256>>>(nullptr, W3);
    k_att<<<attBlocks, 256>>>(as3, ad3);
    k_agg<<<aggBlocks, 256>>>(b3);

    // pool + fc
    k_pool<<<aggBlocks, 256>>>(batch);
    k_fc<<<(Gg * OUTC + 255) / 256, 256>>>(fcW, fcb, out);
}

// round 6
// speedup vs baseline: 1.5502x; 1.0937x over previous
#include <cuda_runtime.h>
#include <math.h>

#define Nn   50000
#define Ee   800000
#define ENb  (Ee + Nn)
#define Cc   128
#define Hh   4
#define Gg   512
#define OUTC 100
#define NEG  0.2f
#define EPSf 1e-16f

typedef unsigned long long ull;

#define PACK2(out, lo, hi) \
    asm("mov.b64 %0, {%1, %2};" : "=l"(out) : "r"(__float_as_uint(lo)), "r"(__float_as_uint(hi)))
#define UNPACK2(lo, hi, in) \
    do { unsigned _ul, _uh; \
         asm("mov.b64 {%0, %1}, %2;" : "=r"(_ul), "=r"(_uh) : "l"(in)); \
         lo = __uint_as_float(_ul); hi = __uint_as_float(_uh); } while (0)
#define FMA2(d, a, b) \
    asm("fma.rn.f32x2 %0, %1, %2, %0;" : "+l"(d) : "l"(a), "l"(b))

// ---- scratch (device globals: no allocations allowed) ----
__device__ __align__(16) float g_feat[Nn * Cc];   // layer output / next layer input
__device__ __align__(16) float g_h[Nn * Cc];      // transformed features (gather source)
__device__ __align__(16) float g_asrc[Nn * Hh];
__device__ __align__(16) float g_adst[Nn * Hh];
__device__ int   g_rowptr[Nn + 1];
__device__ int   g_cursor[Nn];
__device__ int   g_col[ENb];
__device__ __align__(16) float g_sums[Gg * Cc];
__device__ float g_cnt[Gg];

// ---------------- init: deg=1 (self loop), zero pool accumulators ----------------
__global__ void k_init() {
    int i = blockIdx.x * 256 + threadIdx.x;
    if (i < Gg * Cc) g_sums[i] = 0.f;
    if (i < Gg)      g_cnt[i]  = 0.f;
    if (i < Nn)      g_cursor[i] = 1;   // self loop counted
}

// ---------------- histogram over dst ----------------
__global__ void k_hist(const int* __restrict__ ei) {
    int e = blockIdx.x * 256 + threadIdx.x;
    if (e < Ee) {
        int d = ei[Ee + e];
        atomicAdd(&g_cursor[d], 1);
    }
}

// ---------------- single-block exclusive scan (N=50000) ----------------
__global__ void k_scan() {
    __shared__ int s[1024];
    int t = threadIdx.x;
    const int PER = (Nn + 1023) / 1024;   // 49
    int base = t * PER;
    int sum = 0;
    for (int i = 0; i < PER; i++) {
        int idx = base + i;
        if (idx < Nn) sum += g_cursor[idx];
    }
    s[t] = sum;
    __syncthreads();
    for (int o = 1; o < 1024; o <<= 1) {
        int u = (t >= o) ? s[t - o] : 0;
        __syncthreads();
        s[t] += u;
        __syncthreads();
    }
    int off = s[t] - sum;                 // exclusive prefix
    for (int i = 0; i < PER; i++) {
        int idx = base + i;
        if (idx < Nn) {
            int d = g_cursor[idx];
            g_rowptr[idx] = off;
            g_cursor[idx] = off;          // scatter cursor
            off += d;
        }
    }
    if (t == 1023) g_rowptr[Nn] = s[1023];
}

// ---------------- scatter edges + self loops into CSR ----------------
__global__ void k_scatter(const int* __restrict__ ei) {
    int e = blockIdx.x * 256 + threadIdx.x;
    if (e >= ENb) return;
    if (e < Ee) {
        int d = ei[Ee + e];
        int pos = atomicAdd(&g_cursor[d], 1);
        g_col[pos] = ei[e];
    } else {
        int n = e - Ee;
        int pos = atomicAdd(&g_cursor[n], 1);
        g_col[pos] = n;
    }
}

// ---------------- fused GEMM (f32x2) + attention logits ----------------
// g_h[N,128] = X[N,128] @ W[128,128]^T, plus per-head att dots from register accs.
// BM=128, BN=64, BK=32, 256 threads, 8x4 per thread, accumulators packed as
// row-pair f32x2 (fma.rn.f32x2 = 2x fp32 throughput).
template<bool FROM_GLOBAL>
__global__ __launch_bounds__(256) void k_gemm(const float* __restrict__ X,
                                              const float* __restrict__ W,
                                              const float* __restrict__ AS,
                                              const float* __restrict__ AD) {
    __shared__ __align__(16) float ftT[32][136];   // [k][row]
    __shared__ __align__(16) float wtT[32][72];    // [k][col]
    const float* __restrict__ src = FROM_GLOBAL ? (const float*)g_feat : X;
    int t = threadIdx.x;
    int rowBlk = blockIdx.x * 128;
    int colBlk = blockIdx.y * 64;
    int tx = t & 15, ty = t >> 4;
    int r0 = ty << 3;                // 0..120
    int c0 = tx << 2;                // 0..60
    ull acc[4][4];                   // [row-pair][col], lo=row 2jp, hi=row 2jp+1
#pragma unroll
    for (int jp = 0; jp < 4; jp++)
#pragma unroll
        for (int l = 0; l < 4; l++) acc[jp][l] = 0ull;

    for (int kb = 0; kb < 128; kb += 32) {
#pragma unroll
        for (int i = 0; i < 16; i++) {
            int idx = t + i * 256;
            int r = idx >> 5, k = idx & 31;
            int row = rowBlk + r;
            ftT[k][r] = (row < Nn) ? src[row * 128 + kb + k] : 0.f;
        }
#pragma unroll
        for (int i = 0; i < 8; i++) {
            int idx = t + i * 256;
            int c = idx >> 5, k = idx & 31;
            wtT[k][c] = W[(colBlk + c) * 128 + kb + k];
        }
        __syncthreads();
#pragma unroll
        for (int k = 0; k < 32; k++) {
            ulonglong2 a0 = *(const ulonglong2*)&ftT[k][r0];       // rows r0..r0+3
            ulonglong2 a1 = *(const ulonglong2*)&ftT[k][r0 + 4];   // rows r0+4..r0+7
            float4 b = *(const float4*)&wtT[k][c0];
            ull ap[4] = {a0.x, a0.y, a1.x, a1.y};
            ull bp[4];
            PACK2(bp[0], b.x, b.x);
            PACK2(bp[1], b.y, b.y);
            PACK2(bp[2], b.z, b.z);
            PACK2(bp[3], b.w, b.w);
#pragma unroll
            for (int jp = 0; jp < 4; jp++) {
                FMA2(acc[jp][0], ap[jp], bp[0]);
                FMA2(acc[jp][1], ap[jp], bp[1]);
                FMA2(acc[jp][2], ap[jp], bp[2]);
                FMA2(acc[jp][3], ap[jp], bp[3]);
            }
        }
        __syncthreads();
    }

    // unpack accumulators into per-row values
    float rv[8][4];
#pragma unroll
    for (int jp = 0; jp < 4; jp++)
#pragma unroll
        for (int l = 0; l < 4; l++)
            UNPACK2(rv[2 * jp][l], rv[2 * jp + 1][l], acc[jp][l]);

    // att vectors for this thread's 4 columns (all within one head: c0 is 4-aligned,
    // head blocks are 32 wide)
    float4 sv = *(const float4*)&AS[colBlk + c0];
    float4 dv = *(const float4*)&AD[colBlk + c0];
    int head = (blockIdx.y << 1) + (tx >> 3);

#pragma unroll
    for (int j = 0; j < 8; j++) {
        int row = rowBlk + r0 + j;
        float ps = rv[j][0] * sv.x + rv[j][1] * sv.y + rv[j][2] * sv.z + rv[j][3] * sv.w;
        float pd = rv[j][0] * dv.x + rv[j][1] * dv.y + rv[j][2] * dv.z + rv[j][3] * dv.w;
        // reduce over the 8 threads (tx bits 0..2) covering one 32-col head
        ps += __shfl_xor_sync(0xffffffffu, ps, 1);
        pd += __shfl_xor_sync(0xffffffffu, pd, 1);
        ps += __shfl_xor_sync(0xffffffffu, ps, 2);
        pd += __shfl_xor_sync(0xffffffffu, pd, 2);
        ps += __shfl_xor_sync(0xffffffffu, ps, 4);
        pd += __shfl_xor_sync(0xffffffffu, pd, 4);
        if (row < Nn) {
            *(float4*)&g_h[row * 128 + colBlk + c0] =
                make_float4(rv[j][0], rv[j][1], rv[j][2], rv[j][3]);
            if ((tx & 7) == 0) {
                g_asrc[row * 4 + head] = ps;
                g_adst[row * 4 + head] = pd;
            }
        }
    }
}

__device__ __forceinline__ float lrelu(float x) { return x > 0.f ? x : NEG * x; }

// ---------------- per-dst-node softmax + aggregation, single pass ----------------
// exp(a)/sum(exp(a)) == exp(a-m)/sum(exp(a-m)); logits are O(1) so no stabilizer.
__global__ __launch_bounds__(256) void k_agg(const float* __restrict__ bias) {
    int n = (blockIdx.x * 256 + threadIdx.x) >> 5;
    int lane = threadIdx.x & 31;
    if (n >= Nn) return;
    int start = g_rowptr[n], end = g_rowptr[n + 1];
    int head = lane >> 3;
    int ch = lane << 2;
    float adh = g_adst[n * 4 + head];

    float4 acc = make_float4(0.f, 0.f, 0.f, 0.f);
    float den = 0.f;
    int e = start;
    for (; e + 3 < end; e += 4) {
        int s0 = g_col[e], s1 = g_col[e + 1], s2 = g_col[e + 2], s3 = g_col[e + 3];
        float a0 = g_asrc[(s0 << 2) + head];
        float a1 = g_asrc[(s1 << 2) + head];
        float a2 = g_asrc[(s2 << 2) + head];
        float a3 = g_asrc[(s3 << 2) + head];
        float4 h0 = *(const float4*)(g_h + s0 * 128 + ch);
        float4 h1 = *(const float4*)(g_h + s1 * 128 + ch);
        float4 h2 = *(const float4*)(g_h + s2 * 128 + ch);
        float4 h3 = *(const float4*)(g_h + s3 * 128 + ch);
        float w0 = __expf(lrelu(a0 + adh));
        float w1 = __expf(lrelu(a1 + adh));
        float w2 = __expf(lrelu(a2 + adh));
        float w3 = __expf(lrelu(a3 + adh));
        den += (w0 + w1) + (w2 + w3);
        acc.x += (w0 * h0.x + w1 * h1.x) + (w2 * h2.x + w3 * h3.x);
        acc.y += (w0 * h0.y + w1 * h1.y) + (w2 * h2.y + w3 * h3.y);
        acc.z += (w0 * h0.z + w1 * h1.z) + (w2 * h2.z + w3 * h3.z);
        acc.w += (w0 * h0.w + w1 * h1.w) + (w2 * h2.w + w3 * h3.w);
    }
    for (; e < end; e++) {
        int s0 = g_col[e];
        float a0 = g_asrc[(s0 << 2) + head] + adh;
        float4 h0 = *(const float4*)(g_h + s0 * 128 + ch);
        float w0 = __expf(lrelu(a0));
        den += w0;
        acc.x += w0 * h0.x;
        acc.y += w0 * h0.y;
        acc.z += w0 * h0.z;
        acc.w += w0 * h0.w;
    }
    float inv = 1.f / (den + EPSf);
    float4 b4 = *(const float4*)(bias + ch);
    float vx = acc.x * inv + b4.x;
    float vy = acc.y * inv + b4.y;
    float vz = acc.z * inv + b4.z;
    float vw = acc.w * inv + b4.w;
    // ELU
    vx = vx > 0.f ? vx : expm1f(vx);
    vy = vy > 0.f ? vy : expm1f(vy);
    vz = vz > 0.f ? vz : expm1f(vz);
    vw = vw > 0.f ? vw : expm1f(vw);
    *(float4*)&g_feat[n * 128 + ch] = make_float4(vx, vy, vz, vw);
}

// ---------------- global mean pool (atomics over g_feat) ----------------
__global__ __launch_bounds__(256) void k_pool(const int* __restrict__ batch) {
    int n = (blockIdx.x * 256 + threadIdx.x) >> 5;
    int lane = threadIdx.x & 31;
    if (n >= Nn) return;
    int g = batch[n];
    float4 v = *(const float4*)(g_feat + n * 128 + (lane << 2));
    float* sp = &g_sums[g * 128 + (lane << 2)];
    atomicAdd(sp + 0, v.x);
    atomicAdd(sp + 1, v.y);
    atomicAdd(sp + 2, v.z);
    atomicAdd(sp + 3, v.w);
    if (lane == 0) atomicAdd(&g_cnt[g], 1.f);
}

// ---------------- final FC: out[G,100] = (sums/cnt) @ fcW^T + fcb ----------------
__global__ void k_fc(const float* __restrict__ fcW,
                     const float* __restrict__ fcb,
                     float* __restrict__ out) {
    int i = blockIdx.x * 256 + threadIdx.x;
    if (i >= Gg * OUTC) return;
    int g = i / OUTC, o = i - g * OUTC;
    float inv = 1.f / fmaxf(g_cnt[g], 1.f);
    const float* sr = &g_sums[g * 128];
    const float* wr = &fcW[o * 128];
    float s = 0.f;
#pragma unroll
    for (int c = 0; c < 128; c++) s = fmaf(sr[c], wr[c], s);
    out[i] = s * inv + fcb[o];
}

extern "C" void kernel_launch(void* const* d_in, const int* in_sizes, int n_in,
                              void* d_out, int out_size) {
    const float* x     = (const float*)d_in[0];
    const int*   ei    = (const int*)d_in[1];    // int64 in reference -> staged int32
    const int*   batch = (const int*)d_in[2];
    const float* W1 = (const float*)d_in[3];
    const float* as1 = (const float*)d_in[4];
    const float* ad1 = (const float*)d_in[5];
    const float* b1 = (const float*)d_in[6];
    const float* W2 = (const float*)d_in[7];
    const float* as2 = (const float*)d_in[8];
    const float* ad2 = (const float*)d_in[9];
    const float* b2 = (const float*)d_in[10];
    const float* W3 = (const float*)d_in[11];
    const float* as3 = (const float*)d_in[12];
    const float* ad3 = (const float*)d_in[13];
    const float* b3 = (const float*)d_in[14];
    const float* fcW = (const float*)d_in[15];
    const float* fcb = (const float*)d_in[16];
    float* out = (float*)d_out;

    // CSR build (once per call) + pool accumulator zeroing
    k_init<<<256, 256>>>();
    k_hist<<<(Ee + 255) / 256, 256>>>(ei);
    k_scan<<<1, 1024>>>();
    k_scatter<<<(ENb + 255) / 256, 256>>>(ei);

    dim3 gg((Nn + 127) / 128, 2);
    int aggBlocks = (Nn + 7) / 8;

    // layer 1
    k_gemm<false><<<gg, 256>>>(x, W1, as1, ad1);
    k_agg<<<aggBlocks, 256>>>(b1);
    // layer 2
    k_gemm<true><<<gg, 256>>>(nullptr, W2, as2, ad2);
    k_agg<<<aggBlocks, 256>>>(b2);
    // layer 3
    k_gemm<true><<<gg, 256>>>(nullptr, W3, as3, ad3);
    k_agg<<<aggBlocks, 256>>>(b3);

    // pool + fc
    k_pool<<<aggBlocks, 256>>>(batch);
    k_fc<<<(Gg * OUTC + 255) / 256, 256>>>(fcW, fcb, out);
}

// round 7
// speedup vs baseline: 1.7398x; 1.1223x over previous
#include <cuda_runtime.h>
#include <math.h>

#define Nn   50000
#define Ee   800000
#define ENb  (Ee + Nn)
#define Cc   128
#define Hh   4
#define Gg   512
#define OUTC 100
#define NEG  0.2f
#define EPSf 1e-16f

typedef unsigned long long ull;

#define PACK2(out, lo, hi) \
    asm("mov.b64 %0, {%1, %2};" : "=l"(out) : "r"(__float_as_uint(lo)), "r"(__float_as_uint(hi)))
#define UNPACK2(lo, hi, in) \
    do { unsigned _ul, _uh; \
         asm("mov.b64 {%0, %1}, %2;" : "=r"(_ul), "=r"(_uh) : "l"(in)); \
         lo = __uint_as_float(_ul); hi = __uint_as_float(_uh); } while (0)
#define FMA2(d, a, b) \
    asm("fma.rn.f32x2 %0, %1, %2, %0;" : "+l"(d) : "l"(a), "l"(b))

// ---- scratch (device globals: no allocations allowed) ----
__device__ __align__(16) float g_feat[Nn * Cc];   // layer output / next layer input
__device__ __align__(16) float g_h[Nn * Cc];      // transformed features (gather source)
__device__ __align__(16) float g_asrc[Nn * Hh];
__device__ __align__(16) float g_adst[Nn * Hh];
__device__ int   g_rowptr[Nn + 1];
__device__ int   g_cursor[Nn];
__device__ int   g_col[ENb];
__device__ __align__(16) float g_sums[Gg * Cc];
__device__ float g_cnt[Gg];

// ---------------- init: deg=1 (self loop), zero pool accumulators ----------------
__global__ void k_init() {
    int i = blockIdx.x * 256 + threadIdx.x;
    if (i < Gg * Cc) g_sums[i] = 0.f;
    if (i < Gg)      g_cnt[i]  = 0.f;
    if (i < Nn)      g_cursor[i] = 1;   // self loop counted
}

// ---------------- histogram over dst ----------------
__global__ void k_hist(const int* __restrict__ ei) {
    int e = blockIdx.x * 256 + threadIdx.x;
    if (e < Ee) {
        int d = ei[Ee + e];
        atomicAdd(&g_cursor[d], 1);
    }
}

// ---------------- single-block exclusive scan (N=50000) ----------------
__global__ void k_scan() {
    __shared__ int s[1024];
    int t = threadIdx.x;
    const int PER = (Nn + 1023) / 1024;   // 49
    int base = t * PER;
    int sum = 0;
    for (int i = 0; i < PER; i++) {
        int idx = base + i;
        if (idx < Nn) sum += g_cursor[idx];
    }
    s[t] = sum;
    __syncthreads();
    for (int o = 1; o < 1024; o <<= 1) {
        int u = (t >= o) ? s[t - o] : 0;
        __syncthreads();
        s[t] += u;
        __syncthreads();
    }
    int off = s[t] - sum;                 // exclusive prefix
    for (int i = 0; i < PER; i++) {
        int idx = base + i;
        if (idx < Nn) {
            int d = g_cursor[idx];
            g_rowptr[idx] = off;
            g_cursor[idx] = off;          // scatter cursor
            off += d;
        }
    }
    if (t == 1023) g_rowptr[Nn] = s[1023];
}

// ---------------- scatter edges + self loops into CSR ----------------
__global__ void k_scatter(const int* __restrict__ ei) {
    int e = blockIdx.x * 256 + threadIdx.x;
    if (e >= ENb) return;
    if (e < Ee) {
        int d = ei[Ee + e];
        int pos = atomicAdd(&g_cursor[d], 1);
        g_col[pos] = ei[e];
    } else {
        int n = e - Ee;
        int pos = atomicAdd(&g_cursor[n], 1);
        g_col[pos] = n;
    }
}

// ---------------- fused GEMM (f32x2, double-buffered) + attention logits ----------------
// g_h[N,128] = X[N,128] @ W[128,128]^T, plus per-head att dots from register accs.
// BM=128, BN=64, BK=16, 256 threads, 8x4 per thread, f32x2 row-pair accumulators.
// Two-stage smem pipeline: LDG(tile i+1) || FMA(tile i); one sync per tile.
template<bool FROM_GLOBAL>
__global__ __launch_bounds__(256) void k_gemm(const float* __restrict__ X,
                                              const float* __restrict__ W,
                                              const float* __restrict__ AS,
                                              const float* __restrict__ AD) {
    __shared__ __align__(16) float ftT[2][16][132];   // [buf][k][row], stride 132 (2-way max)
    __shared__ __align__(16) float wtT[2][16][68];    // [buf][k][col]
    const float* __restrict__ src = FROM_GLOBAL ? (const float*)g_feat : X;
    int t = threadIdx.x;
    int rowBlk = blockIdx.x * 128;
    int colBlk = blockIdx.y * 64;
    int tx = t & 15, ty = t >> 4;
    int r0 = ty << 3;                // 0..120
    int c0 = tx << 2;                // 0..60

    // loader coordinates
    int lr0 = t >> 2;                // A row for chunk 0 (0..63)
    int lkq = t & 3;                 // k-quad 0..3
    int lc  = t >> 2;                // B col (0..63)

    ull acc[4][4];
#pragma unroll
    for (int jp = 0; jp < 4; jp++)
#pragma unroll
        for (int l = 0; l < 4; l++) acc[jp][l] = 0ull;

    float4 ra[2], rb;
    // prologue: fetch tile 0
    {
        int row0 = rowBlk + lr0;
        int row1 = rowBlk + lr0 + 64;
        ra[0] = (row0 < Nn) ? *(const float4*)&src[row0 * 128 + lkq * 4]
                            : make_float4(0.f, 0.f, 0.f, 0.f);
        ra[1] = (row1 < Nn) ? *(const float4*)&src[row1 * 128 + lkq * 4]
                            : make_float4(0.f, 0.f, 0.f, 0.f);
        rb = *(const float4*)&W[(colBlk + lc) * 128 + lkq * 4];
    }
    // store tile 0
    {
        int kbase = lkq * 4;
        ftT[0][kbase + 0][lr0] = ra[0].x;  ftT[0][kbase + 1][lr0] = ra[0].y;
        ftT[0][kbase + 2][lr0] = ra[0].z;  ftT[0][kbase + 3][lr0] = ra[0].w;
        ftT[0][kbase + 0][lr0 + 64] = ra[1].x;  ftT[0][kbase + 1][lr0 + 64] = ra[1].y;
        ftT[0][kbase + 2][lr0 + 64] = ra[1].z;  ftT[0][kbase + 3][lr0 + 64] = ra[1].w;
        wtT[0][kbase + 0][lc] = rb.x;  wtT[0][kbase + 1][lc] = rb.y;
        wtT[0][kbase + 2][lc] = rb.z;  wtT[0][kbase + 3][lc] = rb.w;
    }
    __syncthreads();

#pragma unroll
    for (int tile = 0; tile < 8; tile++) {
        int cur = tile & 1;
        if (tile < 7) {
            int kb = (tile + 1) * 16;
            int row0 = rowBlk + lr0;
            int row1 = rowBlk + lr0 + 64;
            ra[0] = (row0 < Nn) ? *(const float4*)&src[row0 * 128 + kb + lkq * 4]
                                : make_float4(0.f, 0.f, 0.f, 0.f);
            ra[1] = (row1 < Nn) ? *(const float4*)&src[row1 * 128 + kb + lkq * 4]
                                : make_float4(0.f, 0.f, 0.f, 0.f);
            rb = *(const float4*)&W[(colBlk + lc) * 128 + kb + lkq * 4];
        }
#pragma unroll
        for (int k = 0; k < 16; k++) {
            ulonglong2 a0 = *(const ulonglong2*)&ftT[cur][k][r0];
            ulonglong2 a1 = *(const ulonglong2*)&ftT[cur][k][r0 + 4];
            float4 b = *(const float4*)&wtT[cur][k][c0];
            ull ap[4] = {a0.x, a0.y, a1.x, a1.y};
            ull bp[4];
            PACK2(bp[0], b.x, b.x);
            PACK2(bp[1], b.y, b.y);
            PACK2(bp[2], b.z, b.z);
            PACK2(bp[3], b.w, b.w);
#pragma unroll
            for (int jp = 0; jp < 4; jp++) {
                FMA2(acc[jp][0], ap[jp], bp[0]);
                FMA2(acc[jp][1], ap[jp], bp[1]);
                FMA2(acc[jp][2], ap[jp], bp[2]);
                FMA2(acc[jp][3], ap[jp], bp[3]);
            }
        }
        if (tile < 7) {
            int nxt = cur ^ 1;
            int kbase = lkq * 4;
            ftT[nxt][kbase + 0][lr0] = ra[0].x;  ftT[nxt][kbase + 1][lr0] = ra[0].y;
            ftT[nxt][kbase + 2][lr0] = ra[0].z;  ftT[nxt][kbase + 3][lr0] = ra[0].w;
            ftT[nxt][kbase + 0][lr0 + 64] = ra[1].x;  ftT[nxt][kbase + 1][lr0 + 64] = ra[1].y;
            ftT[nxt][kbase + 2][lr0 + 64] = ra[1].z;  ftT[nxt][kbase + 3][lr0 + 64] = ra[1].w;
            wtT[nxt][kbase + 0][lc] = rb.x;  wtT[nxt][kbase + 1][lc] = rb.y;
            wtT[nxt][kbase + 2][lc] = rb.z;  wtT[nxt][kbase + 3][lc] = rb.w;
            __syncthreads();
        }
    }

    // unpack accumulators into per-row values
    float rv[8][4];
#pragma unroll
    for (int jp = 0; jp < 4; jp++)
#pragma unroll
        for (int l = 0; l < 4; l++)
            UNPACK2(rv[2 * jp][l], rv[2 * jp + 1][l], acc[jp][l]);

    // att vectors for this thread's 4 columns (c0 4-aligned within a 32-wide head)
    float4 sv = *(const float4*)&AS[colBlk + c0];
    float4 dv = *(const float4*)&AD[colBlk + c0];
    int head = (blockIdx.y << 1) + (tx >> 3);

#pragma unroll
    for (int j = 0; j < 8; j++) {
        int row = rowBlk + r0 + j;
        float ps = rv[j][0] * sv.x + rv[j][1] * sv.y + rv[j][2] * sv.z + rv[j][3] * sv.w;
        float pd = rv[j][0] * dv.x + rv[j][1] * dv.y + rv[j][2] * dv.z + rv[j][3] * dv.w;
        ps += __shfl_xor_sync(0xffffffffu, ps, 1);
        pd += __shfl_xor_sync(0xffffffffu, pd, 1);
        ps += __shfl_xor_sync(0xffffffffu, ps, 2);
        pd += __shfl_xor_sync(0xffffffffu, pd, 2);
        ps += __shfl_xor_sync(0xffffffffu, ps, 4);
        pd += __shfl_xor_sync(0xffffffffu, pd, 4);
        if (row < Nn) {
            *(float4*)&g_h[row * 128 + colBlk + c0] =
                make_float4(rv[j][0], rv[j][1], rv[j][2], rv[j][3]);
            if ((tx & 7) == 0) {
                g_asrc[row * 4 + head] = ps;
                g_adst[row * 4 + head] = pd;
            }
        }
    }
}

__device__ __forceinline__ float lrelu(float x) { return x > 0.f ? x : NEG * x; }

// ---------------- per-dst-node softmax + aggregation, single pass ----------------
__global__ __launch_bounds__(256) void k_agg(const float* __restrict__ bias) {
    int n = (blockIdx.x * 256 + threadIdx.x) >> 5;
    int lane = threadIdx.x & 31;
    if (n >= Nn) return;
    int start = g_rowptr[n], end = g_rowptr[n + 1];
    int head = lane >> 3;
    int ch = lane << 2;
    float adh = g_adst[n * 4 + head];

    float4 acc = make_float4(0.f, 0.f, 0.f, 0.f);
    float den = 0.f;
    int e = start;
    for (; e + 3 < end; e += 4) {
        int s0 = g_col[e], s1 = g_col[e + 1], s2 = g_col[e + 2], s3 = g_col[e + 3];
        float a0 = g_asrc[(s0 << 2) + head];
        float a1 = g_asrc[(s1 << 2) + head];
        float a2 = g_asrc[(s2 << 2) + head];
        float a3 = g_asrc[(s3 << 2) + head];
        float4 h0 = *(const float4*)(g_h + s0 * 128 + ch);
        float4 h1 = *(const float4*)(g_h + s1 * 128 + ch);
        float4 h2 = *(const float4*)(g_h + s2 * 128 + ch);
        float4 h3 = *(const float4*)(g_h + s3 * 128 + ch);
        float w0 = __expf(lrelu(a0 + adh));
        float w1 = __expf(lrelu(a1 + adh));
        float w2 = __expf(lrelu(a2 + adh));
        float w3 = __expf(lrelu(a3 + adh));
        den += (w0 + w1) + (w2 + w3);
        acc.x += (w0 * h0.x + w1 * h1.x) + (w2 * h2.x + w3 * h3.x);
        acc.y += (w0 * h0.y + w1 * h1.y) + (w2 * h2.y + w3 * h3.y);
        acc.z += (w0 * h0.z + w1 * h1.z) + (w2 * h2.z + w3 * h3.z);
        acc.w += (w0 * h0.w + w1 * h1.w) + (w2 * h2.w + w3 * h3.w);
    }
    for (; e < end; e++) {
        int s0 = g_col[e];
        float a0 = g_asrc[(s0 << 2) + head] + adh;
        float4 h0 = *(const float4*)(g_h + s0 * 128 + ch);
        float w0 = __expf(lrelu(a0));
        den += w0;
        acc.x += w0 * h0.x;
        acc.y += w0 * h0.y;
        acc.z += w0 * h0.z;
        acc.w += w0 * h0.w;
    }
    float inv = 1.f / (den + EPSf);
    float4 b4 = *(const float4*)(bias + ch);
    float vx = acc.x * inv + b4.x;
    float vy = acc.y * inv + b4.y;
    float vz = acc.z * inv + b4.z;
    float vw = acc.w * inv + b4.w;
    // ELU
    vx = vx > 0.f ? vx : expm1f(vx);
    vy = vy > 0.f ? vy : expm1f(vy);
    vz = vz > 0.f ? vz : expm1f(vz);
    vw = vw > 0.f ? vw : expm1f(vw);
    *(float4*)&g_feat[n * 128 + ch] = make_float4(vx, vy, vz, vw);
}

// ---------------- global mean pool (atomics over g_feat) ----------------
__global__ __launch_bounds__(256) void k_pool(const int* __restrict__ batch) {
    int n = (blockIdx.x * 256 + threadIdx.x) >> 5;
    int lane = threadIdx.x & 31;
    if (n >= Nn) return;
    int g = batch[n];
    float4 v = *(const float4*)(g_feat + n * 128 + (lane << 2));
    float* sp = &g_sums[g * 128 + (lane << 2)];
    atomicAdd(sp + 0, v.x);
    atomicAdd(sp + 1, v.y);
    atomicAdd(sp + 2, v.z);
    atomicAdd(sp + 3, v.w);
    if (lane == 0) atomicAdd(&g_cnt[g], 1.f);
}

// ---------------- final FC: out[G,100] = (sums/cnt) @ fcW^T + fcb ----------------
__global__ void k_fc(const float* __restrict__ fcW,
                     const float* __restrict__ fcb,
                     float* __restrict__ out) {
    int i = blockIdx.x * 256 + threadIdx.x;
    if (i >= Gg * OUTC) return;
    int g = i / OUTC, o = i - g * OUTC;
    float inv = 1.f / fmaxf(g_cnt[g], 1.f);
    const float* sr = &g_sums[g * 128];
    const float* wr = &fcW[o * 128];
    float s = 0.f;
#pragma unroll
    for (int c = 0; c < 128; c++) s = fmaf(sr[c], wr[c], s);
    out[i] = s * inv + fcb[o];
}

extern "C" void kernel_launch(void* const* d_in, const int* in_sizes, int n_in,
                              void* d_out, int out_size) {
    const float* x     = (const float*)d_in[0];
    const int*   ei    = (const int*)d_in[1];    // int64 in reference -> staged int32
    const int*   batch = (const int*)d_in[2];
    const float* W1 = (const float*)d_in[3];
    const float* as1 = (const float*)d_in[4];
    const float* ad1 = (const float*)d_in[5];
    const float* b1 = (const float*)d_in[6];
    const float* W2 = (const float*)d_in[7];
    const float* as2 = (const float*)d_in[8];
    const float* ad2 = (const float*)d_in[9];
    const float* b2 = (const float*)d_in[10];
    const float* W3 = (const float*)d_in[11];
    const float* as3 = (const float*)d_in[12];
    const float* ad3 = (const float*)d_in[13];
    const float* b3 = (const float*)d_in[14];
    const float* fcW = (const float*)d_in[15];
    const float* fcb = (const float*)d_in[16];
    float* out = (float*)d_out;

    // CSR build (once per call) + pool accumulator zeroing
    k_init<<<256, 256>>>();
    k_hist<<<(Ee + 255) / 256, 256>>>(ei);
    k_scan<<<1, 1024>>>();
    k_scatter<<<(ENb + 255) / 256, 256>>>(ei);

    dim3 gg((Nn + 127) / 128, 2);
    int aggBlocks = (Nn + 7) / 8;

    // layer 1
    k_gemm<false><<<gg, 256>>>(x, W1, as1, ad1);
    k_agg<<<aggBlocks, 256>>>(b1);
    // layer 2
    k_gemm<true><<<gg, 256>>>(nullptr, W2, as2, ad2);
    k_agg<<<aggBlocks, 256>>>(b2);
    // layer 3
    k_gemm<true><<<gg, 256>>>(nullptr, W3, as3, ad3);
    k_agg<<<aggBlocks, 256>>>(b3);

    // pool + fc
    k_pool<<<aggBlocks, 256>>>(batch);
    k_fc<<<(Gg * OUTC + 255) / 256, 256>>>(fcW, fcb, out);
}